// round 1
// baseline (speedup 1.0000x reference)
#include <cuda_runtime.h>

#define N_B   4
#define C_CH  256
#define HW    4096
#define NH    4
#define DH    64
#define NPIX  (C_CH * HW)   // 1048576 elements per sample

// ---------------- scratch (static device globals; no allocs) ----------------
__device__ float g_part[N_B][128][2];
__device__ float g_stats[N_B][2];                       // mean, inv_std
__device__ float g_qkv[(size_t)N_B * 3 * C_CH * HW];    // [n][768][4096]
__device__ float g_y[(size_t)N_B * C_CH * HW];          // [n][256][4096]

// ---------------- GroupNorm stats: pass 1 (per-block partials) ----------------
__global__ __launch_bounds__(256) void k_stat1(const float* __restrict__ x) {
    int n = blockIdx.y, part = blockIdx.x, tid = threadIdx.x;
    const float* p = x + (size_t)n * NPIX + (size_t)part * 8192;
    float s = 0.f, q = 0.f;
#pragma unroll
    for (int i = 0; i < 32; i++) { float v = p[i * 256 + tid]; s += v; q += v * v; }
    __shared__ float ss[256], sq[256];
    ss[tid] = s; sq[tid] = q;
    __syncthreads();
    for (int o = 128; o > 0; o >>= 1) {
        if (tid < o) { ss[tid] += ss[tid + o]; sq[tid] += sq[tid + o]; }
        __syncthreads();
    }
    if (tid == 0) { g_part[n][part][0] = ss[0]; g_part[n][part][1] = sq[0]; }
}

// ---------------- GroupNorm stats: pass 2 (deterministic combine) ----------------
__global__ __launch_bounds__(128) void k_stat2() {
    int n = blockIdx.x, tid = threadIdx.x;
    __shared__ float ss[128], sq[128];
    ss[tid] = g_part[n][tid][0]; sq[tid] = g_part[n][tid][1];
    __syncthreads();
    for (int o = 64; o > 0; o >>= 1) {
        if (tid < o) { ss[tid] += ss[tid + o]; sq[tid] += sq[tid + o]; }
        __syncthreads();
    }
    if (tid == 0) {
        float mean = ss[0] / (float)NPIX;
        float var  = sq[0] / (float)NPIX - mean * mean;
        g_stats[n][0] = mean;
        g_stats[n][1] = rsqrtf(var + 1e-5f);
    }
}

// ---------------- QKV GEMM with fused GroupNorm (normalize-on-load) ----------------
// qkv[n][o][p] = sum_c w[o][c] * xn[n][c][p] + b[o],  o in [0,768)
__global__ __launch_bounds__(256) void k_qkv(const float* __restrict__ x,
                                             const float* __restrict__ gamma,
                                             const float* __restrict__ beta,
                                             const float* __restrict__ w,
                                             const float* __restrict__ bias) {
    __shared__ float As[64][20];   // w tile [o][k]
    __shared__ float Bs[16][68];   // xn tile [k][p]
    int n = blockIdx.z, o0 = blockIdx.y * 64, p0 = blockIdx.x * 64;
    int tid = threadIdx.x, tx = tid & 15, ty = tid >> 4;
    float mean = g_stats[n][0], inv = g_stats[n][1];
    float acc[4][4] = {};
    int ar = tid >> 2, ac = (tid & 3) << 2;
    int br = tid >> 4, bc = (tid & 15) << 2;
    for (int k0 = 0; k0 < C_CH; k0 += 16) {
        *(float4*)&As[ar][ac] = *(const float4*)&w[(size_t)(o0 + ar) * C_CH + k0 + ac];
        float g  = gamma[k0 + br] * inv;
        float bb = beta[k0 + br] - mean * g;
        float4 bv = *(const float4*)&x[((size_t)n * C_CH + k0 + br) * HW + p0 + bc];
        bv.x = bv.x * g + bb; bv.y = bv.y * g + bb; bv.z = bv.z * g + bb; bv.w = bv.w * g + bb;
        *(float4*)&Bs[br][bc] = bv;
        __syncthreads();
#pragma unroll
        for (int kk = 0; kk < 16; kk++) {
            float av[4];
#pragma unroll
            for (int i = 0; i < 4; i++) av[i] = As[ty * 4 + i][kk];
            float4 b4 = *(const float4*)&Bs[kk][tx << 2];
            float bvv[4] = {b4.x, b4.y, b4.z, b4.w};
#pragma unroll
            for (int i = 0; i < 4; i++)
#pragma unroll
                for (int j = 0; j < 4; j++) acc[i][j] += av[i] * bvv[j];
        }
        __syncthreads();
    }
    float* dst = g_qkv + ((size_t)n * 768 + o0) * HW + p0;
#pragma unroll
    for (int i = 0; i < 4; i++) {
        int o = ty * 4 + i;
        float bi = bias[o0 + o];
        float4 r = make_float4(acc[i][0] + bi, acc[i][1] + bi, acc[i][2] + bi, acc[i][3] + bi);
        *(float4*)&dst[(size_t)o * HW + (tx << 2)] = r;
    }
}

// ---------------- flash attention: Br=Bc=64, online softmax ----------------
#define ATT_SMEM_FLOATS (64*64 + 64*64 + 64*65 + 64*64 + 192)
#define ATT_SMEM_BYTES  (ATT_SMEM_FLOATS * 4)

__global__ __launch_bounds__(256) void k_att() {
    extern __shared__ float sm[];
    float* Qs  = sm;                 // [64 d][64 pq]   pitch 64
    float* Ks  = Qs + 64 * 64;       // [64 d][64 pk]   pitch 64
    float* Vs  = Ks + 64 * 64;       // [64 d][65]      pitch 65 (column-read safe)
    float* Ss  = Vs + 64 * 65;       // [64 pq][64 pk]  pitch 64
    float* m_s = Ss + 64 * 64;
    float* l_s = m_s + 64;
    float* a_s = l_s + 64;

    int q0 = blockIdx.x * 64, head = blockIdx.y, n = blockIdx.z;
    int tid = threadIdx.x, tx = tid & 15, ty = tid >> 4;
    const float* qp = g_qkv + ((size_t)n * 768 + (head)          * 64) * HW;
    const float* kp = g_qkv + ((size_t)n * 768 + (NH + head)     * 64) * HW;
    const float* vp = g_qkv + ((size_t)n * 768 + (2 * NH + head) * 64) * HW;

    int lr = tid >> 4;            // 0..15
    int lc = (tid & 15) << 2;     // 0..60 step 4
#pragma unroll
    for (int rr = 0; rr < 4; rr++) {
        int d = lr + rr * 16;
        *(float4*)&Qs[d * 64 + lc] = *(const float4*)&qp[(size_t)d * HW + q0 + lc];
    }
    if (tid < 64) { m_s[tid] = -1e30f; l_s[tid] = 0.f; }

    float o[4][4] = {};
    for (int kt = 0; kt < 64; kt++) {
        int k0 = kt * 64;
        __syncthreads();   // prior PV done; Q/m_s ready on first iter
#pragma unroll
        for (int rr = 0; rr < 4; rr++) {
            int d = lr + rr * 16;
            *(float4*)&Ks[d * 64 + lc] = *(const float4*)&kp[(size_t)d * HW + k0 + lc];
            float4 vv = *(const float4*)&vp[(size_t)d * HW + k0 + lc];
            Vs[d * 65 + lc + 0] = vv.x; Vs[d * 65 + lc + 1] = vv.y;
            Vs[d * 65 + lc + 2] = vv.z; Vs[d * 65 + lc + 3] = vv.w;
        }
        __syncthreads();   // tiles ready

        // ---- S = (Q^T K) * dh^-0.5
        float s[4][4] = {};
#pragma unroll 16
        for (int kk = 0; kk < 64; kk++) {
            float4 a4 = *(const float4*)&Qs[kk * 64 + (ty << 2)];
            float4 b4 = *(const float4*)&Ks[kk * 64 + (tx << 2)];
            float av[4] = {a4.x, a4.y, a4.z, a4.w};
            float bv[4] = {b4.x, b4.y, b4.z, b4.w};
#pragma unroll
            for (int i = 0; i < 4; i++)
#pragma unroll
                for (int j = 0; j < 4; j++) s[i][j] += av[i] * bv[j];
        }
        float rm[4];
#pragma unroll
        for (int i = 0; i < 4; i++) {
#pragma unroll
            for (int j = 0; j < 4; j++) s[i][j] *= 0.125f;   // dh^-0.5
            rm[i] = fmaxf(fmaxf(s[i][0], s[i][1]), fmaxf(s[i][2], s[i][3]));
        }
#pragma unroll
        for (int ofs = 1; ofs < 16; ofs <<= 1)
#pragma unroll
            for (int i = 0; i < 4; i++)
                rm[i] = fmaxf(rm[i], __shfl_xor_sync(0xffffffffu, rm[i], ofs));
        if (tx == 0) {
#pragma unroll
            for (int i = 0; i < 4; i++) {
                int r = ty * 4 + i;
                float mo = m_s[r], mn = fmaxf(mo, rm[i]);
                m_s[r] = mn;
                a_s[r] = __expf(mo - mn);
            }
        }
        __syncthreads();   // m/alpha published

        float al[4], rs[4];
#pragma unroll
        for (int i = 0; i < 4; i++) {
            int r = ty * 4 + i;
            float mn = m_s[r];
            al[i] = a_s[r];
            float p0 = __expf(s[i][0] - mn);
            float p1 = __expf(s[i][1] - mn);
            float p2 = __expf(s[i][2] - mn);
            float p3 = __expf(s[i][3] - mn);
            float4 pr = make_float4(p0, p1, p2, p3);
            *(float4*)&Ss[r * 64 + (tx << 2)] = pr;
            rs[i] = p0 + p1 + p2 + p3;
        }
#pragma unroll
        for (int ofs = 1; ofs < 16; ofs <<= 1)
#pragma unroll
            for (int i = 0; i < 4; i++)
                rs[i] += __shfl_xor_sync(0xffffffffu, rs[i], ofs);
        if (tx == 0) {
#pragma unroll
            for (int i = 0; i < 4; i++) {
                int r = ty * 4 + i;
                l_s[r] = l_s[r] * al[i] + rs[i];
            }
        }
#pragma unroll
        for (int i = 0; i < 4; i++)
#pragma unroll
            for (int j = 0; j < 4; j++) o[i][j] *= al[i];
        __syncthreads();   // P published

        // ---- O += P * V    (O[pq][d], a=Ss row broadcast, b=Vs column pitch-65)
#pragma unroll 16
        for (int kk = 0; kk < 64; kk++) {
            float av[4], bv[4];
#pragma unroll
            for (int i = 0; i < 4; i++) av[i] = Ss[(ty * 4 + i) * 64 + kk];
#pragma unroll
            for (int j = 0; j < 4; j++) bv[j] = Vs[(tx * 4 + j) * 65 + kk];
#pragma unroll
            for (int i = 0; i < 4; i++)
#pragma unroll
                for (int j = 0; j < 4; j++) o[i][j] += av[i] * bv[j];
        }
    }

    float linv[4];
#pragma unroll
    for (int i = 0; i < 4; i++) linv[i] = 1.f / l_s[ty * 4 + i];
    float* yp = g_y + ((size_t)n * C_CH + head * 64) * HW;
#pragma unroll
    for (int j = 0; j < 4; j++) {
        int d = tx * 4 + j;
        float4 r = make_float4(o[0][j] * linv[0], o[1][j] * linv[1],
                               o[2][j] * linv[2], o[3][j] * linv[3]);
        *(float4*)&yp[(size_t)d * HW + q0 + (ty << 2)] = r;
    }
}

// ---------------- out projection + bias + residual ----------------
__global__ __launch_bounds__(256) void k_out(const float* __restrict__ x,
                                             const float* __restrict__ w,
                                             const float* __restrict__ bias,
                                             float* __restrict__ out) {
    __shared__ float As[64][20];
    __shared__ float Bs[16][68];
    int n = blockIdx.z, o0 = blockIdx.y * 64, p0 = blockIdx.x * 64;
    int tid = threadIdx.x, tx = tid & 15, ty = tid >> 4;
    float acc[4][4] = {};
    int ar = tid >> 2, ac = (tid & 3) << 2;
    int br = tid >> 4, bc = (tid & 15) << 2;
    for (int k0 = 0; k0 < C_CH; k0 += 16) {
        *(float4*)&As[ar][ac] = *(const float4*)&w[(size_t)(o0 + ar) * C_CH + k0 + ac];
        *(float4*)&Bs[br][bc] =
            *(const float4*)&g_y[((size_t)n * C_CH + k0 + br) * HW + p0 + bc];
        __syncthreads();
#pragma unroll
        for (int kk = 0; kk < 16; kk++) {
            float av[4];
#pragma unroll
            for (int i = 0; i < 4; i++) av[i] = As[ty * 4 + i][kk];
            float4 b4 = *(const float4*)&Bs[kk][tx << 2];
            float bvv[4] = {b4.x, b4.y, b4.z, b4.w};
#pragma unroll
            for (int i = 0; i < 4; i++)
#pragma unroll
                for (int j = 0; j < 4; j++) acc[i][j] += av[i] * bvv[j];
        }
        __syncthreads();
    }
#pragma unroll
    for (int i = 0; i < 4; i++) {
        int o = o0 + ty * 4 + i;
        float bi = bias[o];
        size_t idx = ((size_t)n * C_CH + o) * HW + p0 + (tx << 2);
        float4 xr = *(const float4*)&x[idx];
        float4 r = make_float4(acc[i][0] + bi + xr.x, acc[i][1] + bi + xr.y,
                               acc[i][2] + bi + xr.z, acc[i][3] + bi + xr.w);
        *(float4*)&out[idx] = r;
    }
}

// ---------------- launch ----------------
extern "C" void kernel_launch(void* const* d_in, const int* in_sizes, int n_in,
                              void* d_out, int out_size) {
    (void)in_sizes; (void)n_in; (void)out_size;
    const float* x     = (const float*)d_in[0];
    const float* gamma = (const float*)d_in[1];
    const float* beta  = (const float*)d_in[2];
    const float* w_qkv = (const float*)d_in[3];
    const float* b_qkv = (const float*)d_in[4];
    const float* w_out = (const float*)d_in[5];
    const float* b_out = (const float*)d_in[6];
    float* out = (float*)d_out;

    cudaFuncSetAttribute(k_att, cudaFuncAttributeMaxDynamicSharedMemorySize, ATT_SMEM_BYTES);

    k_stat1<<<dim3(128, N_B), 256>>>(x);
    k_stat2<<<N_B, 128>>>();
    k_qkv<<<dim3(HW / 64, 12, N_B), 256>>>(x, gamma, beta, w_qkv, b_qkv);
    k_att<<<dim3(HW / 64, NH, N_B), 256, ATT_SMEM_BYTES>>>();
    k_out<<<dim3(HW / 64, 4, N_B), 256>>>(x, w_out, b_out, out);
}

// round 3
// speedup vs baseline: 2.0655x; 2.0655x over previous
#include <cuda_runtime.h>

#define N_B   4
#define C_CH  256
#define HW    4096
#define NH    4
#define DH    64
#define NPIX  (C_CH * HW)   // 1048576 elements per sample

// ---------------- scratch (static device globals; no allocs) ----------------
__device__ float g_part[N_B][128][2];
__device__ float g_stats[N_B][2];                       // mean, inv_std
__device__ float g_qkv[(size_t)N_B * 3 * C_CH * HW];    // [n][768][4096]
__device__ float g_y[(size_t)N_B * C_CH * HW];          // [n][256][4096]

// ---------------- GroupNorm stats: pass 1 ----------------
__global__ __launch_bounds__(256) void k_stat1(const float* __restrict__ x) {
    int n = blockIdx.y, part = blockIdx.x, tid = threadIdx.x;
    const float* p = x + (size_t)n * NPIX + (size_t)part * 8192;
    float s = 0.f, q = 0.f;
#pragma unroll
    for (int i = 0; i < 32; i++) { float v = p[i * 256 + tid]; s += v; q += v * v; }
    __shared__ float ss[256], sq[256];
    ss[tid] = s; sq[tid] = q;
    __syncthreads();
    for (int o = 128; o > 0; o >>= 1) {
        if (tid < o) { ss[tid] += ss[tid + o]; sq[tid] += sq[tid + o]; }
        __syncthreads();
    }
    if (tid == 0) { g_part[n][part][0] = ss[0]; g_part[n][part][1] = sq[0]; }
}

// ---------------- GroupNorm stats: pass 2 ----------------
__global__ __launch_bounds__(128) void k_stat2() {
    int n = blockIdx.x, tid = threadIdx.x;
    __shared__ float ss[128], sq[128];
    ss[tid] = g_part[n][tid][0]; sq[tid] = g_part[n][tid][1];
    __syncthreads();
    for (int o = 64; o > 0; o >>= 1) {
        if (tid < o) { ss[tid] += ss[tid + o]; sq[tid] += sq[tid + o]; }
        __syncthreads();
    }
    if (tid == 0) {
        float mean = ss[0] / (float)NPIX;
        float var  = sq[0] / (float)NPIX - mean * mean;
        g_stats[n][0] = mean;
        g_stats[n][1] = rsqrtf(var + 1e-5f);
    }
}

// ---------------- QKV GEMM with fused GroupNorm ----------------
__global__ __launch_bounds__(256) void k_qkv(const float* __restrict__ x,
                                             const float* __restrict__ gamma,
                                             const float* __restrict__ beta,
                                             const float* __restrict__ w,
                                             const float* __restrict__ bias) {
    __shared__ float As[64][20];
    __shared__ float Bs[16][68];
    int n = blockIdx.z, o0 = blockIdx.y * 64, p0 = blockIdx.x * 64;
    int tid = threadIdx.x, tx = tid & 15, ty = tid >> 4;
    float mean = g_stats[n][0], inv = g_stats[n][1];
    float acc[4][4] = {};
    int ar = tid >> 2, ac = (tid & 3) << 2;
    int br = tid >> 4, bc = (tid & 15) << 2;
    for (int k0 = 0; k0 < C_CH; k0 += 16) {
        *(float4*)&As[ar][ac] = *(const float4*)&w[(size_t)(o0 + ar) * C_CH + k0 + ac];
        float g  = gamma[k0 + br] * inv;
        float bb = beta[k0 + br] - mean * g;
        float4 bv = *(const float4*)&x[((size_t)n * C_CH + k0 + br) * HW + p0 + bc];
        bv.x = bv.x * g + bb; bv.y = bv.y * g + bb; bv.z = bv.z * g + bb; bv.w = bv.w * g + bb;
        *(float4*)&Bs[br][bc] = bv;
        __syncthreads();
#pragma unroll
        for (int kk = 0; kk < 16; kk++) {
            float av[4];
#pragma unroll
            for (int i = 0; i < 4; i++) av[i] = As[ty * 4 + i][kk];
            float4 b4 = *(const float4*)&Bs[kk][tx << 2];
            float bvv[4] = {b4.x, b4.y, b4.z, b4.w};
#pragma unroll
            for (int i = 0; i < 4; i++)
#pragma unroll
                for (int j = 0; j < 4; j++) acc[i][j] += av[i] * bvv[j];
        }
        __syncthreads();
    }
    float* dst = g_qkv + ((size_t)n * 768 + o0) * HW + p0;
#pragma unroll
    for (int i = 0; i < 4; i++) {
        int o = ty * 4 + i;
        float bi = bias[o0 + o];
        float4 r = make_float4(acc[i][0] + bi, acc[i][1] + bi, acc[i][2] + bi, acc[i][3] + bi);
        *(float4*)&dst[(size_t)o * HW + (tx << 2)] = r;
    }
}

// ---------------- tf32 mma helpers ----------------
__device__ __forceinline__ unsigned f2tf(float f) {
    unsigned u;
    asm("cvt.rna.tf32.f32 %0, %1;" : "=r"(u) : "f"(f));
    return u;
}
__device__ __forceinline__ void mma_tf32(float c[4], const unsigned a[4],
                                         unsigned b0, unsigned b1) {
    asm volatile(
        "mma.sync.aligned.m16n8k8.row.col.f32.tf32.tf32.f32 "
        "{%0,%1,%2,%3}, {%4,%5,%6,%7}, {%8,%9}, {%0,%1,%2,%3};"
        : "+f"(c[0]), "+f"(c[1]), "+f"(c[2]), "+f"(c[3])
        : "r"(a[0]), "r"(a[1]), "r"(a[2]), "r"(a[3]), "r"(b0), "r"(b1));
}

// ---------------- flash attention via tf32 tensor cores ----------------
// S = Q^T K (M=64 q, N=64 k, Kdim=64 d), online softmax, O = P V.
// 8 warps: warp = qg*2 + ch; qg -> 16 q-rows, ch -> 32-col half.
#define KP 72   // Ks pitch (B-frag QK loads: bank = 8*tq + tg, conflict-free)
#define VP 68   // Vs pitch (B-frag PV loads: bank = 4*tg + tq, conflict-free)
#define PP 68   // Ps pitch (A-frag loads:    bank = 4*tg + tq, conflict-free)
#define ATT2_SMEM_FLOATS (64*KP + 64*VP + 64*PP + 64 + 64 + 128 + 128)
#define ATT2_SMEM_BYTES  (ATT2_SMEM_FLOATS * 4)

__global__ __launch_bounds__(256) void k_att() {
    extern __shared__ float sm[];
    float* Ks   = sm;                 // [d][pk]  pitch KP
    float* Vs   = Ks + 64 * KP;       // [d][pk]  pitch VP
    float* Ps   = Vs + 64 * VP;       // [q][*]   pitch PP (Q staging, then P)
    float* m_s  = Ps + 64 * PP;
    float* l_s  = m_s + 64;
    float* redm = l_s + 64;           // [2][64]
    float* redl = redm + 128;         // [2][64]

    int q0 = blockIdx.x * 64, head = blockIdx.y, n = blockIdx.z;
    int tid = threadIdx.x;
    int warp = tid >> 5, lane = tid & 31;
    int qg = warp >> 1, ch = warp & 1;
    int tg = lane >> 2, tq = lane & 3;
    int r0 = qg * 16 + tg;            // local q row (and +8)

    const float* qp = g_qkv + ((size_t)n * 768 + (head)          * 64) * HW;
    const float* kp = g_qkv + ((size_t)n * 768 + (NH + head)     * 64) * HW;
    const float* vp = g_qkv + ((size_t)n * 768 + (2 * NH + head) * 64) * HW;

    // stage Q to Ps transposed: Ps[q][d]
    int lr = tid >> 4;                // 0..15
    int lc4 = (tid & 15) << 2;        // 0..60 step 4
#pragma unroll
    for (int rr = 0; rr < 4; rr++) {
        int d = lr + rr * 16;
        float4 v = *(const float4*)&qp[(size_t)d * HW + q0 + lc4];
        Ps[(lc4 + 0) * PP + d] = v.x;
        Ps[(lc4 + 1) * PP + d] = v.y;
        Ps[(lc4 + 2) * PP + d] = v.z;
        Ps[(lc4 + 3) * PP + d] = v.w;
    }
    if (tid < 64) { m_s[tid] = -1e30f; l_s[tid] = 0.f; }
    __syncthreads();

    // Q A-fragments resident, pre-scaled by 1/8 (= dh^-0.5)
    unsigned a[8][4];
#pragma unroll
    for (int kf = 0; kf < 8; kf++) {
        int d0 = kf * 8 + tq;
        a[kf][0] = f2tf(0.125f * Ps[r0 * PP + d0]);
        a[kf][1] = f2tf(0.125f * Ps[(r0 + 8) * PP + d0]);
        a[kf][2] = f2tf(0.125f * Ps[r0 * PP + d0 + 4]);
        a[kf][3] = f2tf(0.125f * Ps[(r0 + 8) * PP + d0 + 4]);
    }

    float o[4][4] = {};

    for (int kt = 0; kt < 64; kt++) {
        int k0 = kt * 64;
        __syncthreads();   // prior PV / P reads done; Ks/Vs/Ps reusable
#pragma unroll
        for (int rr = 0; rr < 4; rr++) {
            int d = lr + rr * 16;
            *(float4*)&Ks[d * KP + lc4] = *(const float4*)&kp[(size_t)d * HW + k0 + lc4];
            *(float4*)&Vs[d * VP + lc4] = *(const float4*)&vp[(size_t)d * HW + k0 + lc4];
        }
        __syncthreads();   // tiles ready

        // ---- S = (Q/8)^T K  via tf32 mma
        float sf[4][4] = {};
#pragma unroll
        for (int kf = 0; kf < 8; kf++) {
            int krow = kf * 8 + tq;
#pragma unroll
            for (int nf = 0; nf < 4; nf++) {
                int ncol = ch * 32 + nf * 8 + tg;
                unsigned b0 = f2tf(Ks[krow * KP + ncol]);
                unsigned b1 = f2tf(Ks[(krow + 4) * KP + ncol]);
                mma_tf32(sf[nf], a[kf], b0, b1);
            }
        }

        // ---- row max (rows r0, r0+8), quad shuffle + 2-warp combine
        float mx0 = -1e30f, mx1 = -1e30f;
#pragma unroll
        for (int nf = 0; nf < 4; nf++) {
            mx0 = fmaxf(mx0, fmaxf(sf[nf][0], sf[nf][1]));
            mx1 = fmaxf(mx1, fmaxf(sf[nf][2], sf[nf][3]));
        }
        mx0 = fmaxf(mx0, __shfl_xor_sync(0xffffffffu, mx0, 1));
        mx0 = fmaxf(mx0, __shfl_xor_sync(0xffffffffu, mx0, 2));
        mx1 = fmaxf(mx1, __shfl_xor_sync(0xffffffffu, mx1, 1));
        mx1 = fmaxf(mx1, __shfl_xor_sync(0xffffffffu, mx1, 2));
        redm[ch * 64 + r0]     = mx0;
        redm[ch * 64 + r0 + 8] = mx1;
        __syncthreads();   // redm published

        float mt0 = fmaxf(redm[r0],     redm[64 + r0]);
        float mt1 = fmaxf(redm[r0 + 8], redm[64 + r0 + 8]);
        float mo0 = m_s[r0], mo1 = m_s[r0 + 8];
        float mn0 = fmaxf(mo0, mt0), mn1 = fmaxf(mo1, mt1);
        float al0 = __expf(mo0 - mn0), al1 = __expf(mo1 - mn1);

        float sum0 = 0.f, sum1 = 0.f;
#pragma unroll
        for (int nf = 0; nf < 4; nf++) {
            float p0 = __expf(sf[nf][0] - mn0);
            float p1 = __expf(sf[nf][1] - mn0);
            float p2 = __expf(sf[nf][2] - mn1);
            float p3 = __expf(sf[nf][3] - mn1);
            sum0 += p0 + p1; sum1 += p2 + p3;
            int col = ch * 32 + nf * 8 + 2 * tq;
            *(float2*)&Ps[r0 * PP + col] =
                make_float2(__uint_as_float(f2tf(p0)), __uint_as_float(f2tf(p1)));
            *(float2*)&Ps[(r0 + 8) * PP + col] =
                make_float2(__uint_as_float(f2tf(p2)), __uint_as_float(f2tf(p3)));
        }
        sum0 += __shfl_xor_sync(0xffffffffu, sum0, 1);
        sum0 += __shfl_xor_sync(0xffffffffu, sum0, 2);
        sum1 += __shfl_xor_sync(0xffffffffu, sum1, 1);
        sum1 += __shfl_xor_sync(0xffffffffu, sum1, 2);
        redl[ch * 64 + r0]     = sum0;
        redl[ch * 64 + r0 + 8] = sum1;

        // rescale O
#pragma unroll
        for (int nf = 0; nf < 4; nf++) {
            o[nf][0] *= al0; o[nf][1] *= al0;
            o[nf][2] *= al1; o[nf][3] *= al1;
        }
        __syncthreads();   // P + redl published

        // single-writer stats update (safe: next read of m_s is after next 2 barriers)
        if (ch == 0 && tq == 0) {
            m_s[r0]     = mn0;
            m_s[r0 + 8] = mn1;
            l_s[r0]     = l_s[r0]     * al0 + redl[r0]     + redl[64 + r0];
            l_s[r0 + 8] = l_s[r0 + 8] * al1 + redl[r0 + 8] + redl[64 + r0 + 8];
        }

        // ---- O += P V  via tf32 mma (A from Ps already tf32)
#pragma unroll
        for (int kf = 0; kf < 8; kf++) {
            int pk = kf * 8 + tq;
            unsigned pa[4];
            pa[0] = __float_as_uint(Ps[r0 * PP + pk]);
            pa[1] = __float_as_uint(Ps[(r0 + 8) * PP + pk]);
            pa[2] = __float_as_uint(Ps[r0 * PP + pk + 4]);
            pa[3] = __float_as_uint(Ps[(r0 + 8) * PP + pk + 4]);
#pragma unroll
            for (int nf = 0; nf < 4; nf++) {
                int dv = ch * 32 + nf * 8 + tg;
                unsigned b0 = f2tf(Vs[dv * VP + pk]);
                unsigned b1 = f2tf(Vs[dv * VP + pk + 4]);
                mma_tf32(o[nf], pa, b0, b1);
            }
        }
    }

    __syncthreads();   // final l_s visible
    float linv0 = 1.f / l_s[r0];
    float linv1 = 1.f / l_s[r0 + 8];
    float* yp = g_y + ((size_t)n * C_CH + head * 64) * HW;
#pragma unroll
    for (int nf = 0; nf < 4; nf++) {
        int dv = ch * 32 + nf * 8 + 2 * tq;
        yp[(size_t)dv * HW + q0 + r0]           = o[nf][0] * linv0;
        yp[(size_t)(dv + 1) * HW + q0 + r0]     = o[nf][1] * linv0;
        yp[(size_t)dv * HW + q0 + r0 + 8]       = o[nf][2] * linv1;
        yp[(size_t)(dv + 1) * HW + q0 + r0 + 8] = o[nf][3] * linv1;
    }
}

// ---------------- out projection + bias + residual ----------------
__global__ __launch_bounds__(256) void k_out(const float* __restrict__ x,
                                             const float* __restrict__ w,
                                             const float* __restrict__ bias,
                                             float* __restrict__ out) {
    __shared__ float As[64][20];
    __shared__ float Bs[16][68];
    int n = blockIdx.z, o0 = blockIdx.y * 64, p0 = blockIdx.x * 64;
    int tid = threadIdx.x, tx = tid & 15, ty = tid >> 4;
    float acc[4][4] = {};
    int ar = tid >> 2, ac = (tid & 3) << 2;
    int br = tid >> 4, bc = (tid & 15) << 2;
    for (int k0 = 0; k0 < C_CH; k0 += 16) {
        *(float4*)&As[ar][ac] = *(const float4*)&w[(size_t)(o0 + ar) * C_CH + k0 + ac];
        *(float4*)&Bs[br][bc] =
            *(const float4*)&g_y[((size_t)n * C_CH + k0 + br) * HW + p0 + bc];
        __syncthreads();
#pragma unroll
        for (int kk = 0; kk < 16; kk++) {
            float av[4];
#pragma unroll
            for (int i = 0; i < 4; i++) av[i] = As[ty * 4 + i][kk];
            float4 b4 = *(const float4*)&Bs[kk][tx << 2];
            float bvv[4] = {b4.x, b4.y, b4.z, b4.w};
#pragma unroll
            for (int i = 0; i < 4; i++)
#pragma unroll
                for (int j = 0; j < 4; j++) acc[i][j] += av[i] * bvv[j];
        }
        __syncthreads();
    }
#pragma unroll
    for (int i = 0; i < 4; i++) {
        int o = o0 + ty * 4 + i;
        float bi = bias[o];
        size_t idx = ((size_t)n * C_CH + o) * HW + p0 + (tx << 2);
        float4 xr = *(const float4*)&x[idx];
        float4 r = make_float4(acc[i][0] + bi + xr.x, acc[i][1] + bi + xr.y,
                               acc[i][2] + bi + xr.z, acc[i][3] + bi + xr.w);
        *(float4*)&out[idx] = r;
    }
}

// ---------------- launch ----------------
extern "C" void kernel_launch(void* const* d_in, const int* in_sizes, int n_in,
                              void* d_out, int out_size) {
    (void)in_sizes; (void)n_in; (void)out_size;
    const float* x     = (const float*)d_in[0];
    const float* gamma = (const float*)d_in[1];
    const float* beta  = (const float*)d_in[2];
    const float* w_qkv = (const float*)d_in[3];
    const float* b_qkv = (const float*)d_in[4];
    const float* w_out = (const float*)d_in[5];
    const float* b_out = (const float*)d_in[6];
    float* out = (float*)d_out;

    cudaFuncSetAttribute(k_att, cudaFuncAttributeMaxDynamicSharedMemorySize, ATT2_SMEM_BYTES);

    k_stat1<<<dim3(128, N_B), 256>>>(x);
    k_stat2<<<N_B, 128>>>();
    k_qkv<<<dim3(HW / 64, 12, N_B), 256>>>(x, gamma, beta, w_qkv, b_qkv);
    k_att<<<dim3(HW / 64, NH, N_B), 256, ATT2_SMEM_BYTES>>>();
    k_out<<<dim3(HW / 64, 4, N_B), 256>>>(x, w_out, b_out, out);
}